// round 4
// baseline (speedup 1.0000x reference)
#include <cuda_runtime.h>
#include <cuda_fp16.h>
#include <cstdint>

// ---------------------------------------------------------------------------
// RNNT joiner, fused single-pass GEMM:
//   out[m, v] = sum_d relu(src[b,t,d]+tgt[b,u,d]) * W[v,d] + bias[v]
// M=65536, N=1024, K=1024. mma.sync m16n8k16 fp16 (fp32 acc) is the HW floor
// (~512 MAC/cyc/SM on the sm_103 legacy pipe); everything else hides under it:
// A tile = 2 src rows x 64 tgt rows is rebuilt in-kernel from tiny fp32
// staging slices (cp.async), one stage ahead of HMMA consumption.
// ---------------------------------------------------------------------------

#define B_ 4
#define T_ 256
#define U_ 64
#define D_ 1024
#define V_ 1024
#define M_ (B_ * T_ * U_)

#define TILE_M 128
#define TILE_N 128
#define TILE_K 32
#define KITERS (D_ / TILE_K) /* 32 */
#define NTHREADS 256
#define NSTAGE 4

#define PITCH 80                      /* fp16 tile row: 64B + 16B pad (ldmatrix-safe) */
#define STAGE_BYTES (128 * PITCH)     /* 10240 */
#define FPITCH 144                    /* fp32 staging row: 128B + 16B pad (LDS-safe) */
#define TGT_STAGE (64 * FPITCH)       /* 9216 */
#define SRC_STAGE 512                 /* 2 rows x 144B, rounded */

// smem: B[4] | A[2] | tgt[4] | src[4]
#define OFF_B 0
#define OFF_A (NSTAGE * STAGE_BYTES)                   /* 40960 */
#define OFF_T (OFF_A + 2 * STAGE_BYTES)                /* 61440 */
#define OFF_S (OFF_T + NSTAGE * TGT_STAGE)             /* 98304 */
#define SMEM_DYN (OFF_S + NSTAGE * SRC_STAGE)          /* 100352 */

__device__ __forceinline__ uint32_t smem_u32(const void* p) {
    uint32_t a;
    asm("{ .reg .u64 t; cvta.to.shared.u64 t, %1; cvt.u32.u64 %0, t; }" : "=r"(a) : "l"(p));
    return a;
}

__device__ __forceinline__ void cp16(uint32_t saddr, const void* g) {
    asm volatile("cp.async.cg.shared.global [%0], [%1], 16;" :: "r"(saddr), "l"(g) : "memory");
}
#define CP_COMMIT() asm volatile("cp.async.commit_group;" ::: "memory")
#define CP_WAIT(n)  asm volatile("cp.async.wait_group %0;" :: "n"(n) : "memory")

__device__ __forceinline__ void ldsm_x4(uint32_t (&r)[4], uint32_t addr) {
    asm volatile("ldmatrix.sync.aligned.m8n8.x4.shared.b16 {%0,%1,%2,%3}, [%4];"
                 : "=r"(r[0]), "=r"(r[1]), "=r"(r[2]), "=r"(r[3]) : "r"(addr));
}

__device__ __forceinline__ void mma16816(float (&d)[4], const uint32_t (&a)[4],
                                         uint32_t b0, uint32_t b1) {
    asm volatile(
        "mma.sync.aligned.m16n8k16.row.col.f32.f16.f16.f32 "
        "{%0,%1,%2,%3}, {%4,%5,%6,%7}, {%8,%9}, {%0,%1,%2,%3};"
        : "+f"(d[0]), "+f"(d[1]), "+f"(d[2]), "+f"(d[3])
        : "r"(a[0]), "r"(a[1]), "r"(a[2]), "r"(a[3]), "r"(b0), "r"(b1));
}

__device__ __forceinline__ void sts128(uint32_t addr, uint32_t x, uint32_t y,
                                       uint32_t z, uint32_t w) {
    asm volatile("st.shared.v4.b32 [%0], {%1,%2,%3,%4};"
                 :: "r"(addr), "r"(x), "r"(y), "r"(z), "r"(w) : "memory");
}

__device__ __forceinline__ uint32_t h2u(__half2 h) { return *reinterpret_cast<uint32_t*>(&h); }

// W pre-converted to fp16, row-major [V][D]  (2 MB static device buffer)
__device__ __align__(16) __half g_Wh[(size_t)V_ * D_];

// convert W + write the appended lengths tail in one aux kernel
__global__ void prep_kernel(const float* __restrict__ W,
                            const int* __restrict__ sl, const int* __restrict__ tl,
                            float* __restrict__ tail_out, int ntail) {
    int i = blockIdx.x * blockDim.x + threadIdx.x;  // over V*D/4
    float4 v = reinterpret_cast<const float4*>(W)[i];
    __half2* dst = reinterpret_cast<__half2*>(g_Wh);
    dst[2 * i + 0] = __floats2half2_rn(v.x, v.y);
    dst[2 * i + 1] = __floats2half2_rn(v.z, v.w);
    if (blockIdx.x == 0 && threadIdx.x < (unsigned)ntail) {
        int k = threadIdx.x;
        int val = (k < B_) ? sl[k] : ((k < 2 * B_) ? tl[k - B_] : 0);
        tail_out[k] = (float)val;
    }
}

__global__ void __launch_bounds__(NTHREADS, 2) joiner_gemm(
    const float* __restrict__ src, const float* __restrict__ tgt,
    const float* __restrict__ bias, float* __restrict__ out) {
    extern __shared__ __align__(128) char smem[];
    const uint32_t S0 = smem_u32(smem);

    const int tid = threadIdx.x;
    const int wid = tid >> 5, lane = tid & 31;
    const int nt = blockIdx.x;   // 0..7  (nt-fast: 8 CTAs share src/tgt slices in L2)
    const int mt = blockIdx.y;   // 0..511
    const int b = mt >> 7;
    const int t0 = (mt & 127) * 2;

    // ---- B load-role: thread -> (row r, 16-half chunk hf) ----
    const int r = tid >> 1;
    const int hf = tid & 1;
    const __half* wrow = g_Wh + ((size_t)(nt * TILE_N + r)) * D_ + hf * 16;
    const uint32_t fill_off = (uint32_t)r * PITCH + hf * 32;

    // ---- fp32 staging load-role ----
    // tgt: 512 cp16 per stage -> 2 per thread: idx = tid*2+i, row=idx>>3, seg=idx&7
    const int tg_row0 = (tid * 2) >> 3;
    const int tg_seg0 = (tid * 2) & 7;
    const float* tgtb = tgt + ((size_t)(b * U_)) * D_;
    const float* srcb = src + ((size_t)(b * T_ + t0)) * D_;

    // ---- build-role: thread -> (row r, hf) computes 16 halfs of A ----
    const int t_loc = r >> 6;     // 0..1
    const int u_loc = r & 63;

    // ---- mma-role mapping ----
    const int wm = wid & 3;
    const int wn = wid >> 2;
    const int m0w = wm * 32;
    const int n0w = wn * 64;
    const uint32_t a_ld_off = (uint32_t)(m0w + (lane & 15)) * PITCH + (lane >> 4) * 16;
    const uint32_t b_row = (uint32_t)(n0w + (lane & 7) + ((lane & 16) >> 1));
    const uint32_t b_ld_off = b_row * PITCH + ((lane >> 3) & 1) * 16;

    float acc[2][8][4];
#pragma unroll
    for (int mi = 0; mi < 2; mi++)
#pragma unroll
        for (int ni = 0; ni < 8; ni++)
#pragma unroll
            for (int q = 0; q < 4; q++) acc[mi][ni][q] = 0.f;

    // issue all cp.async for one k-stage (B fp16 + src/tgt fp32 slices)
    auto loadStage = [&](int s, int kt) {
        const int k0 = kt * TILE_K;
        // B tile: 2 cp16 per thread
        uint32_t db = S0 + OFF_B + s * STAGE_BYTES + fill_off;
        const __half* gb = wrow + k0;
        cp16(db, gb);
        cp16(db + 16, gb + 8);
        // tgt fp32 slice: 2 cp16 per thread
        uint32_t dt = S0 + OFF_T + s * TGT_STAGE;
        cp16(dt + (uint32_t)tg_row0 * FPITCH + tg_seg0 * 16,
             tgtb + (size_t)tg_row0 * D_ + k0 + tg_seg0 * 4);
        int row1 = (tid * 2 + 1) >> 3, seg1 = (tid * 2 + 1) & 7;
        cp16(dt + (uint32_t)row1 * FPITCH + seg1 * 16,
             tgtb + (size_t)row1 * D_ + k0 + seg1 * 4);
        // src fp32 slice: threads 0..15
        if (tid < 16) {
            int sr = tid >> 3, seg = tid & 7;
            cp16(S0 + OFF_S + s * SRC_STAGE + (uint32_t)sr * FPITCH + seg * 16,
                 srcb + (size_t)sr * D_ + k0 + seg * 4);
        }
    };

    // build fp16 A tile for stage kt from staged fp32 (slot s = kt&3 of staging,
    // into A double-buffer slot kt&1)
    auto buildA = [&](int kt) {
        const int s = kt & (NSTAGE - 1);
        const uint32_t sp = S0 + OFF_S + s * SRC_STAGE + (uint32_t)t_loc * FPITCH + hf * 64;
        const uint32_t tp = S0 + OFF_T + s * TGT_STAGE + (uint32_t)u_loc * FPITCH + hf * 64;
        float4 s0, s1, s2, s3, g0, g1, g2, g3;
        asm volatile("ld.shared.v4.f32 {%0,%1,%2,%3}, [%4];"
                     : "=f"(s0.x), "=f"(s0.y), "=f"(s0.z), "=f"(s0.w) : "r"(sp));
        asm volatile("ld.shared.v4.f32 {%0,%1,%2,%3}, [%4];"
                     : "=f"(s1.x), "=f"(s1.y), "=f"(s1.z), "=f"(s1.w) : "r"(sp + 16));
        asm volatile("ld.shared.v4.f32 {%0,%1,%2,%3}, [%4];"
                     : "=f"(s2.x), "=f"(s2.y), "=f"(s2.z), "=f"(s2.w) : "r"(sp + 32));
        asm volatile("ld.shared.v4.f32 {%0,%1,%2,%3}, [%4];"
                     : "=f"(s3.x), "=f"(s3.y), "=f"(s3.z), "=f"(s3.w) : "r"(sp + 48));
        asm volatile("ld.shared.v4.f32 {%0,%1,%2,%3}, [%4];"
                     : "=f"(g0.x), "=f"(g0.y), "=f"(g0.z), "=f"(g0.w) : "r"(tp));
        asm volatile("ld.shared.v4.f32 {%0,%1,%2,%3}, [%4];"
                     : "=f"(g1.x), "=f"(g1.y), "=f"(g1.z), "=f"(g1.w) : "r"(tp + 16));
        asm volatile("ld.shared.v4.f32 {%0,%1,%2,%3}, [%4];"
                     : "=f"(g2.x), "=f"(g2.y), "=f"(g2.z), "=f"(g2.w) : "r"(tp + 32));
        asm volatile("ld.shared.v4.f32 {%0,%1,%2,%3}, [%4];"
                     : "=f"(g3.x), "=f"(g3.y), "=f"(g3.z), "=f"(g3.w) : "r"(tp + 48));
        __half2 h0 = __floats2half2_rn(fmaxf(s0.x + g0.x, 0.f), fmaxf(s0.y + g0.y, 0.f));
        __half2 h1 = __floats2half2_rn(fmaxf(s0.z + g0.z, 0.f), fmaxf(s0.w + g0.w, 0.f));
        __half2 h2 = __floats2half2_rn(fmaxf(s1.x + g1.x, 0.f), fmaxf(s1.y + g1.y, 0.f));
        __half2 h3 = __floats2half2_rn(fmaxf(s1.z + g1.z, 0.f), fmaxf(s1.w + g1.w, 0.f));
        __half2 h4 = __floats2half2_rn(fmaxf(s2.x + g2.x, 0.f), fmaxf(s2.y + g2.y, 0.f));
        __half2 h5 = __floats2half2_rn(fmaxf(s2.z + g2.z, 0.f), fmaxf(s2.w + g2.w, 0.f));
        __half2 h6 = __floats2half2_rn(fmaxf(s3.x + g3.x, 0.f), fmaxf(s3.y + g3.y, 0.f));
        __half2 h7 = __floats2half2_rn(fmaxf(s3.z + g3.z, 0.f), fmaxf(s3.w + g3.w, 0.f));
        uint32_t a = S0 + OFF_A + (kt & 1) * STAGE_BYTES + fill_off;
        sts128(a,      h2u(h0), h2u(h1), h2u(h2), h2u(h3));
        sts128(a + 16, h2u(h4), h2u(h5), h2u(h6), h2u(h7));
    };

    // ---- prologue: stages 0,1,2 in flight; build A(0) ----
#pragma unroll
    for (int s = 0; s < NSTAGE - 1; s++) {
        loadStage(s, s);
        CP_COMMIT();
    }
    CP_WAIT(2);          // stage 0 complete
    __syncthreads();
    buildA(0);

#pragma unroll 1
    for (int kt = 0; kt < KITERS; kt++) {
        const int cur = kt & (NSTAGE - 1);
        CP_WAIT(1);      // stage kt+1 complete (only newest group may be pending)
        __syncthreads(); // A(kt) visible; A-buf (kt+1)&1 and stage (kt+3)&3 reusable
        if (kt + NSTAGE - 1 < KITERS)
            loadStage((kt + NSTAGE - 1) & (NSTAGE - 1), kt + NSTAGE - 1);
        CP_COMMIT();
        if (kt + 1 < KITERS) buildA(kt + 1);

        const uint32_t Ab = S0 + OFF_A + (kt & 1) * STAGE_BYTES;
        const uint32_t Bt = S0 + OFF_B + cur * STAGE_BYTES;
#pragma unroll
        for (int k16 = 0; k16 < 2; k16++) {
            const uint32_t kb = k16 * 32;
            uint32_t bfr[4][4];
#pragma unroll
            for (int p = 0; p < 4; p++)
                ldsm_x4(bfr[p], Bt + (uint32_t)(p * 16) * PITCH + b_ld_off + kb);
#pragma unroll
            for (int mi = 0; mi < 2; mi++) {
                uint32_t af[4];
                ldsm_x4(af, Ab + a_ld_off + (uint32_t)(mi * 16) * PITCH + kb);
#pragma unroll
                for (int ni = 0; ni < 8; ni++)
                    mma16816(acc[mi][ni], af, bfr[ni >> 1][(ni & 1) * 2],
                             bfr[ni >> 1][(ni & 1) * 2 + 1]);
            }
        }
    }

    // ---- epilogue: add bias, write fp32 ----
    const int g = lane >> 2;
    const int tig = lane & 3;
    const int gn0 = nt * TILE_N + n0w;
    float2 bb[8];
#pragma unroll
    for (int ni = 0; ni < 8; ni++)
        bb[ni] = *reinterpret_cast<const float2*>(bias + gn0 + ni * 8 + tig * 2);

    const size_t rowbase = (size_t)mt * TILE_M + m0w;
#pragma unroll
    for (int mi = 0; mi < 2; mi++) {
        size_t r0 = rowbase + mi * 16 + g;
        size_t r1 = r0 + 8;
#pragma unroll
        for (int ni = 0; ni < 8; ni++) {
            float* p0 = out + r0 * (size_t)V_ + gn0 + ni * 8 + tig * 2;
            float* p1 = out + r1 * (size_t)V_ + gn0 + ni * 8 + tig * 2;
            *reinterpret_cast<float2*>(p0) =
                make_float2(acc[mi][ni][0] + bb[ni].x, acc[mi][ni][1] + bb[ni].y);
            *reinterpret_cast<float2*>(p1) =
                make_float2(acc[mi][ni][2] + bb[ni].x, acc[mi][ni][3] + bb[ni].y);
        }
    }
}

extern "C" void kernel_launch(void* const* d_in, const int* in_sizes, int n_in,
                              void* d_out, int out_size) {
    const float* src  = (const float*)d_in[0];
    const int*   slen = (const int*)d_in[1];
    const float* tgt  = (const float*)d_in[2];
    const int*   tlen = (const int*)d_in[3];
    const float* W    = (const float*)d_in[4];
    const float* bias = (const float*)d_in[5];
    float* out = (float*)d_out;

    long long main_elems = (long long)M_ * V_;
    int ntail = 0;
    if ((long long)out_size > main_elems) {
        ntail = (int)((long long)out_size - main_elems);
        if (ntail > 32) ntail = 32;
    }
    prep_kernel<<<(V_ * D_ / 4) / 256, 256>>>(W, slen, tlen, out + main_elems, ntail);

    cudaFuncSetAttribute(joiner_gemm, cudaFuncAttributeMaxDynamicSharedMemorySize, SMEM_DYN);
    dim3 grid(V_ / TILE_N, M_ / TILE_M);  // (8, 512) nt-fast
    joiner_gemm<<<grid, NTHREADS, SMEM_DYN>>>(src, tgt, bias, out);
}